// round 1
// baseline (speedup 1.0000x reference)
#include <cuda_runtime.h>
#include <math.h>

// ---------------------------------------------------------------------------
// QuantumHybridCNN: fused conv1+pool+conv2+pool+fc -> scratch h,
// then head kernel: pre -> tanh -> 4-qubit statevector sim -> post -> sigmoid
//
// Inputs (metadata order):
//  0 x        (B,64)      f32
//  1 conv1_w  (32,1,3)    f32
//  2 conv1_b  (32,)       f32
//  3 conv2_w  (64,32,3)   f32
//  4 conv2_b  (64,)       f32
//  5 fc_w     (1024,64)   f32
//  6 fc_b     (64,)       f32
//  7 pre_w    (64,4)      f32
//  8 pre_b    (4,)        f32
//  9 q_params (24,)       f32
// 10 post_w   (4,1)       f32
// 11 post_b   (1,)        f32
// Output: (B,1) f32
// ---------------------------------------------------------------------------

#define B_MAX   32768
#define ROWS    8
#define THREADS 256

__device__ float g_h[B_MAX * 64];   // fc output scratch (8 MB)

// shared memory layout (float offsets)
#define OFF_X    0          // 8*64          = 512
#define OFF_A1   512        // 8*32*34       = 8704  (halo at [0] and [33])
#define OFF_W2   9216       // 32*3*64       = 6144  (layout [ic][k][oc])
#define OFF_A2   15360      // 8*1024        = 8192
#define OFF_FW   OFF_A1     // fc tile 128*64 = 8192 (aliases A1, dead by then)
#define OFF_C1W  23552      // 96
#define OFF_C1B  23648      // 32
#define OFF_C2B  23680      // 64
#define SMEM_FLOATS 23744   // 94976 bytes -> 2 blocks/SM

__global__ __launch_bounds__(THREADS, 2)
void fused_cnn_fc(const float* __restrict__ x,
                  const float* __restrict__ c1w, const float* __restrict__ c1b,
                  const float* __restrict__ c2w, const float* __restrict__ c2b,
                  const float* __restrict__ fcw, const float* __restrict__ fcb)
{
    extern __shared__ float sm[];
    const int tid  = threadIdx.x;
    const int row0 = blockIdx.x * ROWS;

    // ---- cooperative loads -------------------------------------------------
    for (int i = tid; i < ROWS * 64; i += THREADS)
        sm[OFF_X + i] = x[row0 * 64 + i];
    for (int i = tid; i < 96; i += THREADS) sm[OFF_C1W + i] = c1w[i];
    for (int i = tid; i < 32; i += THREADS) sm[OFF_C1B + i] = c1b[i];
    for (int i = tid; i < 64; i += THREADS) sm[OFF_C2B + i] = c2b[i];
    // conv2_w (o,ic,k) -> smem [ic][k][oc]
    for (int s = tid; s < 6144; s += THREADS) {
        int ic  = s / 192;
        int rem = s - ic * 192;
        int k   = rem >> 6;
        int o   = rem & 63;
        sm[OFF_W2 + s] = c2w[(o * 32 + ic) * 3 + k];
    }
    // zero a1 halos
    for (int i = tid; i < ROWS * 32; i += THREADS) {
        sm[OFF_A1 + i * 34 + 0]  = 0.f;
        sm[OFF_A1 + i * 34 + 33] = 0.f;
    }
    __syncthreads();

    // ---- stage 1: conv1 (pad 1) + relu + maxpool2 -> a1[r][c][1..32] -------
    for (int it = tid; it < ROWS * 32 * 32; it += THREADS) {
        int p = it & 31;
        int c = (it >> 5) & 31;
        int r = it >> 10;
        const float* xr = sm + OFF_X + r * 64;
        float w0 = sm[OFF_C1W + c * 3 + 0];
        float w1 = sm[OFF_C1W + c * 3 + 1];
        float w2 = sm[OFF_C1W + c * 3 + 2];
        float b  = sm[OFF_C1B + c];
        int l0 = 2 * p;
        float xm = (l0 > 0)      ? xr[l0 - 1] : 0.f;
        float xa = xr[l0];
        float xb = xr[l0 + 1];
        float xc = (l0 + 2 < 64) ? xr[l0 + 2] : 0.f;
        float y0 = fmaf(w2, xb, fmaf(w1, xa, fmaf(w0, xm, b)));
        float y1 = fmaf(w2, xc, fmaf(w1, xb, fmaf(w0, xa, b)));
        sm[OFF_A1 + (r * 32 + c) * 34 + p + 1] = fmaxf(fmaxf(y0, y1), 0.f);
    }
    __syncthreads();

    // ---- stage 2: conv2 (pad 1) + relu + maxpool2 -> a2 --------------------
    // thread = (half, r, p2): computes 32 output channels for the pool pair
    {
        const int half = tid >> 7;          // 0..1 (oc half)
        const int r    = (tid >> 4) & 7;    // 0..7
        const int p2   = tid & 15;          // 0..15 pooled position

        float acc0[32], acc1[32];
        #pragma unroll
        for (int o = 0; o < 32; o++) {
            float b = sm[OFF_C2B + half * 32 + o];
            acc0[o] = b; acc1[o] = b;
        }

        const float* a1r = sm + OFF_A1 + (r * 32) * 34;
        #pragma unroll 1
        for (int ic = 0; ic < 32; ic++) {
            const float* ap = a1r + ic * 34 + 2 * p2;   // halo base
            float x0 = ap[0], x1 = ap[1], x2 = ap[2], x3 = ap[3];
            const float4* w0p = (const float4*)(sm + OFF_W2 + (ic * 3 + 0) * 64 + half * 32);
            const float4* w1p = w0p + 16;   // +64 floats
            const float4* w2p = w0p + 32;
            #pragma unroll
            for (int q = 0; q < 8; q++) {
                float4 w0 = w0p[q], w1 = w1p[q], w2 = w2p[q];
                acc0[4*q+0] = fmaf(w2.x, x2, fmaf(w1.x, x1, fmaf(w0.x, x0, acc0[4*q+0])));
                acc1[4*q+0] = fmaf(w2.x, x3, fmaf(w1.x, x2, fmaf(w0.x, x1, acc1[4*q+0])));
                acc0[4*q+1] = fmaf(w2.y, x2, fmaf(w1.y, x1, fmaf(w0.y, x0, acc0[4*q+1])));
                acc1[4*q+1] = fmaf(w2.y, x3, fmaf(w1.y, x2, fmaf(w0.y, x1, acc1[4*q+1])));
                acc0[4*q+2] = fmaf(w2.z, x2, fmaf(w1.z, x1, fmaf(w0.z, x0, acc0[4*q+2])));
                acc1[4*q+2] = fmaf(w2.z, x3, fmaf(w1.z, x2, fmaf(w0.z, x1, acc1[4*q+2])));
                acc0[4*q+3] = fmaf(w2.w, x2, fmaf(w1.w, x1, fmaf(w0.w, x0, acc0[4*q+3])));
                acc1[4*q+3] = fmaf(w2.w, x3, fmaf(w1.w, x2, fmaf(w0.w, x1, acc1[4*q+3])));
            }
        }
        float* a2r = sm + OFF_A2 + r * 1024;
        #pragma unroll
        for (int o = 0; o < 32; o++) {
            float v = fmaxf(fmaxf(acc0[o], acc1[o]), 0.f);
            a2r[(half * 32 + o) * 16 + p2] = v;   // flat = oc*16 + p
        }
    }

    // ---- stage 3: fc (1024 -> 64) + relu -> g_h ----------------------------
    {
        const int rr   = tid >> 5;       // warp = row
        const int lane = tid & 31;
        const int j0   = lane * 2;
        float accA = __ldg(fcb + j0);
        float accB = __ldg(fcb + j0 + 1);
        const float* a2row = sm + OFF_A2 + rr * 1024;

        for (int t = 0; t < 8; t++) {
            __syncthreads();     // a2 complete / previous tile consumed
            const float4* gsrc = (const float4*)(fcw + t * 128 * 64);
            float4* sdst = (float4*)(sm + OFF_FW);
            for (int i = tid; i < 2048; i += THREADS) sdst[i] = gsrc[i];
            __syncthreads();
            const float* a2p = a2row + t * 128;
            #pragma unroll 8
            for (int f = 0; f < 128; f++) {
                float a = a2p[f];
                float2 w = *(const float2*)(sm + OFF_FW + f * 64 + j0);
                accA = fmaf(a, w.x, accA);
                accB = fmaf(a, w.y, accB);
            }
        }
        g_h[(row0 + rr) * 64 + j0]     = fmaxf(accA, 0.f);
        g_h[(row0 + rr) * 64 + j0 + 1] = fmaxf(accB, 0.f);
    }
}

// ---------------------------------------------------------------------------
// head kernel: pre(64->4) + tanh*pi/2 + 4-qubit circuit + post(4->1) + sigmoid
// one thread per row; 16-amplitude state lives in registers.
// ---------------------------------------------------------------------------
__global__ void head_kernel(const float* __restrict__ prew,
                            const float* __restrict__ preb,
                            const float* __restrict__ qp,
                            const float* __restrict__ postw,
                            const float* __restrict__ postb,
                            float* __restrict__ out, int B)
{
    __shared__ float qc[24], qs[24];
    const int tid = threadIdx.x;
    if (tid < 24) {
        float s, c;
        sincosf(qp[tid] * 0.5f, &s, &c);
        qc[tid] = c; qs[tid] = s;
    }
    __syncthreads();

    const int row = blockIdx.x * blockDim.x + tid;
    if (row >= B) return;

    // pre: q_in = tanh(h @ pre_w + pre_b) * pi/2
    const float4* hp = (const float4*)(g_h + (size_t)row * 64);
    float4 acc = *(const float4*)preb;
    #pragma unroll
    for (int j4 = 0; j4 < 16; j4++) {
        float4 h4 = hp[j4];
        float4 wa = __ldg((const float4*)prew + (j4 * 4 + 0));
        float4 wb = __ldg((const float4*)prew + (j4 * 4 + 1));
        float4 wc = __ldg((const float4*)prew + (j4 * 4 + 2));
        float4 wd = __ldg((const float4*)prew + (j4 * 4 + 3));
        acc.x = fmaf(h4.x, wa.x, acc.x); acc.y = fmaf(h4.x, wa.y, acc.y);
        acc.z = fmaf(h4.x, wa.z, acc.z); acc.w = fmaf(h4.x, wa.w, acc.w);
        acc.x = fmaf(h4.y, wb.x, acc.x); acc.y = fmaf(h4.y, wb.y, acc.y);
        acc.z = fmaf(h4.y, wb.z, acc.z); acc.w = fmaf(h4.y, wb.w, acc.w);
        acc.x = fmaf(h4.z, wc.x, acc.x); acc.y = fmaf(h4.z, wc.y, acc.y);
        acc.z = fmaf(h4.z, wc.z, acc.z); acc.w = fmaf(h4.z, wc.w, acc.w);
        acc.x = fmaf(h4.w, wd.x, acc.x); acc.y = fmaf(h4.w, wd.y, acc.y);
        acc.z = fmaf(h4.w, wd.z, acc.z); acc.w = fmaf(h4.w, wd.w, acc.w);
    }
    const float PI_2 = 1.57079632679489662f;
    float th[4] = { tanhf(acc.x) * PI_2, tanhf(acc.y) * PI_2,
                    tanhf(acc.z) * PI_2, tanhf(acc.w) * PI_2 };

    // statevector: index bit layout wire0->8, wire1->4, wire2->2, wire3->1
    float st[16];
    #pragma unroll
    for (int i = 0; i < 16; i++) st[i] = 0.25f;

    // input RY layer
    #pragma unroll
    for (int w = 0; w < 4; w++) {
        float s, c;
        sincosf(th[w] * 0.5f, &s, &c);
        const int m = 8 >> w;
        #pragma unroll
        for (int i = 0; i < 16; i++) {
            if (!(i & m)) {
                int j = i | m;
                float a = st[i], b = st[j];
                st[i] = c * a - s * b;
                st[j] = s * a + c * b;
            }
        }
    }

    // 6 variational layers
    #pragma unroll
    for (int k = 0; k < 6; k++) {
        // CNOT(0,1): ctrl mask 8, tgt mask 4
        #pragma unroll
        for (int i = 0; i < 16; i++)
            if ((i & 8) && !(i & 4)) { float t = st[i]; st[i] = st[i | 4]; st[i | 4] = t; }
        // CNOT(2,3): ctrl mask 2, tgt mask 1
        #pragma unroll
        for (int i = 0; i < 16; i++)
            if ((i & 2) && !(i & 1)) { float t = st[i]; st[i] = st[i | 1]; st[i | 1] = t; }
        // CNOT(1,2): ctrl mask 4, tgt mask 2
        #pragma unroll
        for (int i = 0; i < 16; i++)
            if ((i & 4) && !(i & 2)) { float t = st[i]; st[i] = st[i | 2]; st[i | 2] = t; }
        // RY on all wires with fixed params
        #pragma unroll
        for (int w = 0; w < 4; w++) {
            float c = qc[k * 4 + w], s = qs[k * 4 + w];
            const int m = 8 >> w;
            #pragma unroll
            for (int i = 0; i < 16; i++) {
                if (!(i & m)) {
                    int j = i | m;
                    float a = st[i], b = st[j];
                    st[i] = c * a - s * b;
                    st[j] = s * a + c * b;
                }
            }
        }
    }

    // <Z_q> and head
    float z0 = 0.f, z1 = 0.f, z2 = 0.f, z3 = 0.f;
    #pragma unroll
    for (int i = 0; i < 16; i++) {
        float p = st[i] * st[i];
        z0 += (i & 8) ? -p : p;
        z1 += (i & 4) ? -p : p;
        z2 += (i & 2) ? -p : p;
        z3 += (i & 1) ? -p : p;
    }
    float t = __ldg(postb);
    t = fmaf(z0, __ldg(postw + 0), t);
    t = fmaf(z1, __ldg(postw + 1), t);
    t = fmaf(z2, __ldg(postw + 2), t);
    t = fmaf(z3, __ldg(postw + 3), t);
    out[row] = 1.f / (1.f + expf(-t));
}

extern "C" void kernel_launch(void* const* d_in, const int* in_sizes, int n_in,
                              void* d_out, int out_size)
{
    const float* x     = (const float*)d_in[0];
    const float* c1w   = (const float*)d_in[1];
    const float* c1b   = (const float*)d_in[2];
    const float* c2w   = (const float*)d_in[3];
    const float* c2b   = (const float*)d_in[4];
    const float* fcw   = (const float*)d_in[5];
    const float* fcb   = (const float*)d_in[6];
    const float* prew  = (const float*)d_in[7];
    const float* preb  = (const float*)d_in[8];
    const float* qp    = (const float*)d_in[9];
    const float* postw = (const float*)d_in[10];
    const float* postb = (const float*)d_in[11];

    const int B = in_sizes[0] / 64;
    const size_t smem = SMEM_FLOATS * sizeof(float);

    cudaFuncSetAttribute(fused_cnn_fc,
                         cudaFuncAttributeMaxDynamicSharedMemorySize, (int)smem);

    fused_cnn_fc<<<B / ROWS, THREADS, smem>>>(x, c1w, c1b, c2w, c2b, fcw, fcb);
    head_kernel<<<(B + 255) / 256, 256>>>(prew, preb, qp, postw, postb,
                                          (float*)d_out, B);
}

// round 3
// speedup vs baseline: 3.0479x; 3.0479x over previous
#include <cuda_runtime.h>
#include <math.h>

// ---------------------------------------------------------------------------
// QuantumHybridCNN — tensor-core (tf32 mma.sync) version.
//
// K1: conv1+pool (scalar) -> im2col smem -> conv2 as tf32 GEMM (M=128,N=64,K=96)
//     -> bias+relu+maxpool -> g_a2 scratch (pos-major: [b][p*64+oc], tf32-rounded)
// K2: fc as tf32 GEMM (M=128 tile, N=64, K=1024, weights permuted on staging)
//     -> bias+relu -> h in smem -> fused quantum head -> sigmoid -> out
// ---------------------------------------------------------------------------

#define B_MAX 32768

__device__ float g_a2[B_MAX * 1024];   // pooled conv2 output scratch (134 MB)

// ---- helpers ---------------------------------------------------------------
__device__ __forceinline__ unsigned f2tf32(float f) {
    unsigned u; asm("cvt.rna.tf32.f32 %0, %1;" : "=r"(u) : "f"(f)); return u;
}
__device__ __forceinline__ float tf32f(float f) {   // round f to tf32, keep as float
    return __uint_as_float(f2tf32(f));
}
__device__ __forceinline__ void mma_tf32(float* c, unsigned a0, unsigned a1,
                                         unsigned a2, unsigned a3,
                                         unsigned b0, unsigned b1) {
    asm volatile(
        "mma.sync.aligned.m16n8k8.row.col.f32.tf32.tf32.f32 "
        "{%0,%1,%2,%3},{%4,%5,%6,%7},{%8,%9},{%0,%1,%2,%3};\n"
        : "+f"(c[0]), "+f"(c[1]), "+f"(c[2]), "+f"(c[3])
        : "r"(a0), "r"(a1), "r"(a2), "r"(a3), "r"(b0), "r"(b1));
}
__device__ __forceinline__ unsigned ldu(const float* p) {
    return __float_as_uint(*p);
}

// ===========================================================================
// K1: conv1 + pool + conv2(mma) + pool  ->  g_a2
// block = 4 input rows, 256 threads (8 warps)
// smem floats:
//   A  im2col  [128][100]   @ 0      (12800)
//   W  conv2w  [96][72]     @ 12800  (6912)   kcol = ic*3+k, tf32
//   X  input   [4][64]      @ 19712  (256)
//   C1W        [96]         @ 19968
//   C1B        [32]         @ 20064
//   C2B        [64]         @ 20096   -> total 20160 floats = 80640 B
// ===========================================================================
#define K1_SMEM_FLOATS 20160

__global__ __launch_bounds__(256, 2)
void k1_conv(const float* __restrict__ x,
             const float* __restrict__ c1w, const float* __restrict__ c1b,
             const float* __restrict__ c2w, const float* __restrict__ c2b)
{
    extern __shared__ float sm[];
    float* A   = sm;
    float* W   = sm + 12800;
    float* X   = sm + 19712;
    float* C1W = sm + 19968;
    float* C1B = sm + 20064;
    float* C2B = sm + 20096;

    const int tid  = threadIdx.x;
    const int wid  = tid >> 5;
    const int lane = tid & 31;
    const int row0 = blockIdx.x * 4;

    // ---- cooperative staging ----------------------------------------------
    X[tid] = x[row0 * 64 + tid];                       // 256 = 4*64
    if (tid < 96) C1W[tid] = c1w[tid];
    if (tid < 32) C1B[tid] = c1b[tid];
    if (tid < 64) C2B[tid] = c2b[tid];
    // conv2_w (oc,ic,k) -> W[(ic*3+k)*72 + oc], tf32-rounded; coalesced reads
    for (int g = tid; g < 6144; g += 256) {
        int oc  = g / 96;
        int rem = g - oc * 96;          // ic*3 + k
        W[rem * 72 + oc] = tf32f(c2w[g]);
    }
    // zero im2col halo columns: q=0/k=0 and q=31/k=2
    {
        int r  = tid >> 6;
        int ic = (tid >> 1) & 31;
        if (tid & 1) A[(r * 32 + 31) * 100 + ic * 3 + 2] = 0.f;
        else         A[(r * 32 +  0) * 100 + ic * 3 + 0] = 0.f;
    }
    __syncthreads();

    // ---- conv1 + relu + maxpool2 -> im2col (ic fastest: conflict-free STS) -
    for (int it = tid; it < 4096; it += 256) {
        int ic = it & 31;
        int p  = (it >> 5) & 31;
        int r  = it >> 10;
        const float* xr = X + r * 64;
        float w0 = C1W[ic * 3 + 0], w1 = C1W[ic * 3 + 1], w2 = C1W[ic * 3 + 2];
        float b  = C1B[ic];
        int l0 = 2 * p;
        float xm = (p > 0)  ? xr[l0 - 1] : 0.f;
        float xa = xr[l0];
        float xb = xr[l0 + 1];
        float xc = (p < 31) ? xr[l0 + 2] : 0.f;
        float y0 = fmaf(w2, xb, fmaf(w1, xa, fmaf(w0, xm, b)));
        float y1 = fmaf(w2, xc, fmaf(w1, xb, fmaf(w0, xa, b)));
        float v  = tf32f(fmaxf(fmaxf(y0, y1), 0.f));
        // a1[r][p][ic] -> A[r*32+q][ic*3+k] for q+k-1 == p
        int mb = r * 32;
        if (p < 31) A[(mb + p + 1) * 100 + ic * 3 + 0] = v;
                    A[(mb + p    ) * 100 + ic * 3 + 1] = v;
        if (p > 0)  A[(mb + p - 1) * 100 + ic * 3 + 2] = v;
    }
    __syncthreads();

    // ---- conv2 GEMM: [128 x 96] x [96 x 64] via tf32 mma ------------------
    const int mg = wid & 3;          // m-group: 32 rows = one input row
    const int ng = wid >> 2;         // n-group: 32 cols
    float c[2][4][4] = {};

    #pragma unroll
    for (int ks = 0; ks < 12; ks++) {
        int kk = ks * 8;
        unsigned a[2][4];
        #pragma unroll
        for (int t = 0; t < 2; t++) {
            const float* ap = A + (mg * 32 + t * 16 + (lane >> 2)) * 100
                                + kk + (lane & 3);
            a[t][0] = ldu(ap);       a[t][1] = ldu(ap + 800);
            a[t][2] = ldu(ap + 4);   a[t][3] = ldu(ap + 804);
        }
        #pragma unroll
        for (int n = 0; n < 4; n++) {
            const float* bp = W + (kk + (lane & 3)) * 72
                                + ng * 32 + n * 8 + (lane >> 2);
            unsigned b0 = ldu(bp), b1 = ldu(bp + 4 * 72);
            mma_tf32(c[0][n], a[0][0], a[0][1], a[0][2], a[0][3], b0, b1);
            mma_tf32(c[1][n], a[1][0], a[1][1], a[1][2], a[1][3], b0, b1);
        }
    }

    // ---- bias + relu + maxpool2 (shfl) -> g_a2 pos-major ------------------
    const int grow = row0 + mg;
    float* dst = g_a2 + (size_t)grow * 1024;
    #pragma unroll
    for (int t = 0; t < 2; t++) {
        #pragma unroll
        for (int n = 0; n < 4; n++) {
            int oc0 = ng * 32 + n * 8 + (lane & 3) * 2;
            float b0 = C2B[oc0], b1 = C2B[oc0 + 1];
            float v0 = fmaxf(c[t][n][0] + b0, 0.f);
            float v1 = fmaxf(c[t][n][1] + b1, 0.f);
            float v2 = fmaxf(c[t][n][2] + b0, 0.f);
            float v3 = fmaxf(c[t][n][3] + b1, 0.f);
            v0 = fmaxf(v0, __shfl_xor_sync(0xffffffffu, v0, 4));
            v1 = fmaxf(v1, __shfl_xor_sync(0xffffffffu, v1, 4));
            v2 = fmaxf(v2, __shfl_xor_sync(0xffffffffu, v2, 4));
            v3 = fmaxf(v3, __shfl_xor_sync(0xffffffffu, v3, 4));
            if (!(lane & 4)) {
                int p = t * 8 + (lane >> 3);
                float2 w01 = make_float2(tf32f(v0), tf32f(v1));
                float2 w23 = make_float2(tf32f(v2), tf32f(v3));
                *(float2*)(dst + p * 64 + oc0)       = w01;
                *(float2*)(dst + (p + 4) * 64 + oc0) = w23;
            }
        }
    }
}

// ===========================================================================
// K2: fc GEMM (M=128 tile) + fused quantum head
// smem floats:
//   A  a2 tile / h   [128][68]  @ 0      (8704)
//   W  fcw chunk     [64][72]   @ 8704   (4608)
//   QC [24] @ 13312, QS [24] @ 13336    -> total 13360 floats = 53440 B
// ===========================================================================
#define K2_SMEM_FLOATS 13360

__global__ __launch_bounds__(256, 2)
void k2_fc_head(const float* __restrict__ fcw, const float* __restrict__ fcb,
                const float* __restrict__ prew, const float* __restrict__ preb,
                const float* __restrict__ qp,
                const float* __restrict__ postw, const float* __restrict__ postb,
                float* __restrict__ out)
{
    extern __shared__ float sm[];
    float* A  = sm;            // [128][68]
    float* W  = sm + 8704;     // [64][72]
    float* QC = sm + 13312;
    float* QS = sm + 13336;

    const int tid  = threadIdx.x;
    const int wid  = tid >> 5;
    const int lane = tid & 31;
    const int m0   = blockIdx.x * 128;

    if (tid < 24) {
        float s, cc;
        sincosf(qp[tid] * 0.5f, &s, &cc);
        QC[tid] = cc; QS[tid] = s;
    }

    const int mg = wid & 3;
    const int ng = wid >> 2;
    float c[2][4][4] = {};

    for (int ch = 0; ch < 16; ch++) {
        __syncthreads();
        // stage A: 128 rows x 64-col k-chunk from g_a2 (already tf32-rounded)
        #pragma unroll
        for (int i = 0; i < 8; i++) {
            int idx = tid + i * 256;
            int r = idx >> 4, kv = idx & 15;
            *(float4*)(A + r * 68 + kv * 4) =
                *(const float4*)(g_a2 + (size_t)(m0 + r) * 1024 + ch * 64 + kv * 4);
        }
        // stage W: permuted fc_w — k-index (p*64+oc) with p=ch: row = kk*16+ch
        #pragma unroll
        for (int i = 0; i < 4; i++) {
            int idx = tid + i * 256;
            int kk = idx >> 4, jv = idx & 15;
            float4 w = __ldg((const float4*)(fcw + (kk * 16 + ch) * 64 + jv * 4));
            w.x = tf32f(w.x); w.y = tf32f(w.y); w.z = tf32f(w.z); w.w = tf32f(w.w);
            *(float4*)(W + kk * 72 + jv * 4) = w;
        }
        __syncthreads();

        #pragma unroll
        for (int ks = 0; ks < 8; ks++) {
            int kk = ks * 8;
            unsigned a[2][4];
            #pragma unroll
            for (int t = 0; t < 2; t++) {
                const float* ap = A + (mg * 32 + t * 16 + (lane >> 2)) * 68
                                    + kk + (lane & 3);
                a[t][0] = ldu(ap);       a[t][1] = ldu(ap + 8 * 68);
                a[t][2] = ldu(ap + 4);   a[t][3] = ldu(ap + 8 * 68 + 4);
            }
            #pragma unroll
            for (int n = 0; n < 4; n++) {
                const float* bp = W + (kk + (lane & 3)) * 72
                                    + ng * 32 + n * 8 + (lane >> 2);
                unsigned b0 = ldu(bp), b1 = ldu(bp + 4 * 72);
                mma_tf32(c[0][n], a[0][0], a[0][1], a[0][2], a[0][3], b0, b1);
                mma_tf32(c[1][n], a[1][0], a[1][1], a[1][2], a[1][3], b0, b1);
            }
        }
    }
    __syncthreads();

    // ---- bias + relu -> h in smem (reuse A, stride 68) --------------------
    #pragma unroll
    for (int t = 0; t < 2; t++) {
        #pragma unroll
        for (int n = 0; n < 4; n++) {
            int j0 = ng * 32 + n * 8 + (lane & 3) * 2;
            int m  = mg * 32 + t * 16 + (lane >> 2);
            float b0 = __ldg(fcb + j0), b1 = __ldg(fcb + j0 + 1);
            *(float2*)(A + m * 68 + j0) =
                make_float2(fmaxf(c[t][n][0] + b0, 0.f), fmaxf(c[t][n][1] + b1, 0.f));
            *(float2*)(A + (m + 8) * 68 + j0) =
                make_float2(fmaxf(c[t][n][2] + b0, 0.f), fmaxf(c[t][n][3] + b1, 0.f));
        }
    }
    __syncthreads();

    // ---- quantum head: one thread per row ---------------------------------
    if (tid < 128) {
        const float* hrow = A + tid * 68;
        float4 acc = *(const float4*)preb;
        #pragma unroll
        for (int j4 = 0; j4 < 16; j4++) {
            float4 h4 = *(const float4*)(hrow + j4 * 4);
            float4 wa = __ldg((const float4*)prew + (j4 * 4 + 0));
            float4 wb = __ldg((const float4*)prew + (j4 * 4 + 1));
            float4 wc = __ldg((const float4*)prew + (j4 * 4 + 2));
            float4 wd = __ldg((const float4*)prew + (j4 * 4 + 3));
            acc.x = fmaf(h4.x, wa.x, acc.x); acc.y = fmaf(h4.x, wa.y, acc.y);
            acc.z = fmaf(h4.x, wa.z, acc.z); acc.w = fmaf(h4.x, wa.w, acc.w);
            acc.x = fmaf(h4.y, wb.x, acc.x); acc.y = fmaf(h4.y, wb.y, acc.y);
            acc.z = fmaf(h4.y, wb.z, acc.z); acc.w = fmaf(h4.y, wb.w, acc.w);
            acc.x = fmaf(h4.z, wc.x, acc.x); acc.y = fmaf(h4.z, wc.y, acc.y);
            acc.z = fmaf(h4.z, wc.z, acc.z); acc.w = fmaf(h4.z, wc.w, acc.w);
            acc.x = fmaf(h4.w, wd.x, acc.x); acc.y = fmaf(h4.w, wd.y, acc.y);
            acc.z = fmaf(h4.w, wd.z, acc.z); acc.w = fmaf(h4.w, wd.w, acc.w);
        }
        const float PI_2 = 1.57079632679489662f;
        float th[4] = { tanhf(acc.x) * PI_2, tanhf(acc.y) * PI_2,
                        tanhf(acc.z) * PI_2, tanhf(acc.w) * PI_2 };

        float st[16];
        #pragma unroll
        for (int i = 0; i < 16; i++) st[i] = 0.25f;

        #pragma unroll
        for (int w = 0; w < 4; w++) {
            float s, cc;
            sincosf(th[w] * 0.5f, &s, &cc);
            const int m = 8 >> w;
            #pragma unroll
            for (int i = 0; i < 16; i++) {
                if (!(i & m)) {
                    int j = i | m;
                    float aa = st[i], bb = st[j];
                    st[i] = cc * aa - s * bb;
                    st[j] = s * aa + cc * bb;
                }
            }
        }
        #pragma unroll
        for (int k = 0; k < 6; k++) {
            #pragma unroll
            for (int i = 0; i < 16; i++)
                if ((i & 8) && !(i & 4)) { float tv = st[i]; st[i] = st[i | 4]; st[i | 4] = tv; }
            #pragma unroll
            for (int i = 0; i < 16; i++)
                if ((i & 2) && !(i & 1)) { float tv = st[i]; st[i] = st[i | 1]; st[i | 1] = tv; }
            #pragma unroll
            for (int i = 0; i < 16; i++)
                if ((i & 4) && !(i & 2)) { float tv = st[i]; st[i] = st[i | 2]; st[i | 2] = tv; }
            #pragma unroll
            for (int w = 0; w < 4; w++) {
                float cc = QC[k * 4 + w], s = QS[k * 4 + w];
                const int m = 8 >> w;
                #pragma unroll
                for (int i = 0; i < 16; i++) {
                    if (!(i & m)) {
                        int j = i | m;
                        float aa = st[i], bb = st[j];
                        st[i] = cc * aa - s * bb;
                        st[j] = s * aa + cc * bb;
                    }
                }
            }
        }
        float z0 = 0.f, z1 = 0.f, z2 = 0.f, z3 = 0.f;
        #pragma unroll
        for (int i = 0; i < 16; i++) {
            float p = st[i] * st[i];
            z0 += (i & 8) ? -p : p;
            z1 += (i & 4) ? -p : p;
            z2 += (i & 2) ? -p : p;
            z3 += (i & 1) ? -p : p;
        }
        float tacc = __ldg(postb);
        tacc = fmaf(z0, __ldg(postw + 0), tacc);
        tacc = fmaf(z1, __ldg(postw + 1), tacc);
        tacc = fmaf(z2, __ldg(postw + 2), tacc);
        tacc = fmaf(z3, __ldg(postw + 3), tacc);
        out[m0 + tid] = 1.f / (1.f + expf(-tacc));
    }
}

// ===========================================================================
extern "C" void kernel_launch(void* const* d_in, const int* in_sizes, int n_in,
                              void* d_out, int out_size)
{
    const float* x     = (const float*)d_in[0];
    const float* c1w   = (const float*)d_in[1];
    const float* c1b   = (const float*)d_in[2];
    const float* c2w   = (const float*)d_in[3];
    const float* c2b   = (const float*)d_in[4];
    const float* fcw   = (const float*)d_in[5];
    const float* fcb   = (const float*)d_in[6];
    const float* prew  = (const float*)d_in[7];
    const float* preb  = (const float*)d_in[8];
    const float* qp    = (const float*)d_in[9];
    const float* postw = (const float*)d_in[10];
    const float* postb = (const float*)d_in[11];

    const int B = in_sizes[0] / 64;

    const int s1 = K1_SMEM_FLOATS * sizeof(float);
    const int s2 = K2_SMEM_FLOATS * sizeof(float);
    cudaFuncSetAttribute(k1_conv, cudaFuncAttributeMaxDynamicSharedMemorySize, s1);
    cudaFuncSetAttribute(k2_fc_head, cudaFuncAttributeMaxDynamicSharedMemorySize, s2);

    k1_conv<<<B / 4, 256, s1>>>(x, c1w, c1b, c2w, c2b);
    k2_fc_head<<<B / 128, 256, s2>>>(fcw, fcb, prew, preb, qp, postw, postb,
                                     (float*)d_out);
}

// round 5
// speedup vs baseline: 4.6488x; 1.5253x over previous
#include <cuda_runtime.h>
#include <cuda_fp16.h>
#include <math.h>

// ---------------------------------------------------------------------------
// QuantumHybridCNN — fp16 tensor-core version (m16n8k16, fp32 accumulate).
//
// K0: one-shot weight prep: conv2_w -> g_c2wt (half, [oc][s*32+ic], pad 104)
//                           fc_w    -> g_fcwt (half, [j][p*64+oc])
// K1: 32 rows/block: conv1+pool (scalar fp32) -> a1 half in smem (zero guards)
//     conv2 = 3 shifted fp16 GEMMs (M=32pos x N=64 x K=96) -> bias+relu+pool
//     -> g_a2h (half, pos-major [b][p*64+oc])
// K2: fc GEMM (128 rows/block, K=1024, cp.async double-buffered staging)
//     -> bias+relu -> h smem -> fused quantum head -> sigmoid -> out
// ---------------------------------------------------------------------------

#define B_MAX 32768

__device__ __align__(16) __half g_a2h[B_MAX * 1024];   // 64 MB
__device__ __align__(16) __half g_fcwt[64 * 1024];     // 128 KB
__device__ __align__(16) __half g_c2wt[64 * 104];      // 13.3 KB

// ---- helpers ---------------------------------------------------------------
__device__ __forceinline__ void mma_f16(float* c, unsigned a0, unsigned a1,
                                        unsigned a2, unsigned a3,
                                        unsigned b0, unsigned b1) {
    asm volatile(
        "mma.sync.aligned.m16n8k16.row.col.f32.f16.f16.f32 "
        "{%0,%1,%2,%3},{%4,%5,%6,%7},{%8,%9},{%0,%1,%2,%3};\n"
        : "+f"(c[0]), "+f"(c[1]), "+f"(c[2]), "+f"(c[3])
        : "r"(a0), "r"(a1), "r"(a2), "r"(a3), "r"(b0), "r"(b1));
}
__device__ __forceinline__ unsigned ldh2(const __half* p) {
    return *(const unsigned*)p;
}
__device__ __forceinline__ void cpa16(void* dst, const void* src) {
    unsigned d = (unsigned)__cvta_generic_to_shared(dst);
    asm volatile("cp.async.cg.shared.global [%0], [%1], 16;\n" :: "r"(d), "l"(src));
}

// ===========================================================================
// K0: weight prep
// ===========================================================================
__global__ void k0_setup(const float* __restrict__ c2w,
                         const float* __restrict__ fcw)
{
    int idx = blockIdx.x * 256 + threadIdx.x;
    if (idx < 6144) {                       // conv2_w (oc,ic,s) -> [oc][s*32+ic]
        int oc = idx / 96, rem = idx - oc * 96;   // rem = s*32+ic
        int s = rem >> 5, ic = rem & 31;
        g_c2wt[oc * 104 + rem] = __float2half_rn(c2w[(oc * 32 + ic) * 3 + s]);
    }
    int f = idx - 6144;
    if (f >= 0 && f < 65536) {              // fc_w [k=oc*16+p][j] -> [j][p*64+oc]
        int k = f >> 6, j = f & 63;
        int oc = k >> 4, p = k & 15;
        g_fcwt[j * 1024 + p * 64 + oc] = __float2half_rn(fcw[f]);
    }
}

// ===========================================================================
// K1: 32 rows/block. smem bytes:
//   A1  half [32][34][40] @ 0       (87040)   pos 0/33 = zero guards
//   Wt  half [64][104]    @ 87040   (13312)
//   Xf  f32  [32][64]     @ 100352  (8192)
//   C1W f32 [96] @108544, C1B [32] @108928, C2B [64] @109056 -> 109312 B
// ===========================================================================
#define K1_SMEM 109312

__global__ __launch_bounds__(256, 2)
void k1_conv(const float* __restrict__ x,
             const float* __restrict__ c1w, const float* __restrict__ c1b,
             const float* __restrict__ c2b)
{
    extern __shared__ __align__(16) unsigned char smraw[];
    __half* A1  = (__half*)smraw;
    __half* Wt  = (__half*)(smraw + 87040);
    float*  Xf  = (float*)(smraw + 100352);
    float*  C1W = (float*)(smraw + 108544);
    float*  C1B = (float*)(smraw + 108928);
    float*  C2B = (float*)(smraw + 109056);

    const int tid  = threadIdx.x;
    const int wid  = tid >> 5;
    const int lane = tid & 31;
    const int qrow = lane >> 2;
    const int qc   = lane & 3;
    const int row0 = blockIdx.x * 32;

    // ---- staging -----------------------------------------------------------
    {
        const float4* xs = (const float4*)(x + row0 * 64);
        float4* xd = (float4*)Xf;
        xd[tid] = xs[tid]; xd[tid + 256] = xs[tid + 256];   // 512 float4
    }
    if (tid < 96) C1W[tid] = c1w[tid];
    if (tid < 32) C1B[tid] = c1b[tid];
    if (tid < 64) C2B[tid] = c2b[tid];
    {   // Wt copy: 832 uint4
        const uint4* src = (const uint4*)g_c2wt;
        uint4* dst = (uint4*)Wt;
        #pragma unroll
        for (int i = 0; i < 4; i++) {
            int idx = tid + i * 256;
            if (idx < 832) dst[idx] = src[idx];
        }
    }
    // zero guard rows (pos 0 and 33, cols 0..31)
    #pragma unroll
    for (int i = 0; i < 4; i++) {
        int idx = tid + i * 256;            // 1024 half2 slots
        int r = idx >> 5, rest = idx & 31;
        int pos = (rest & 16) ? 33 : 0;
        int icp = rest & 15;
        *(unsigned*)(A1 + r * 1360 + pos * 40 + icp * 2) = 0u;
    }
    __syncthreads();

    // ---- conv1 + relu + maxpool2 -> A1 (fp16) ------------------------------
    {
        const int icp = tid >> 4, pp = tid & 15;
        const int ic0 = icp * 2;
        const float w00 = C1W[ic0*3], w01 = C1W[ic0*3+1], w02 = C1W[ic0*3+2];
        const float w10 = C1W[ic0*3+3], w11 = C1W[ic0*3+4], w12 = C1W[ic0*3+5];
        const float b0 = C1B[ic0], b1 = C1B[ic0+1];
        for (int r = 0; r < 32; r++) {
            const float* xr = Xf + r * 64;
            #pragma unroll
            for (int g = 0; g < 2; g++) {
                int p = pp + g * 16;
                int l0 = 2 * p;
                float xm = (p > 0)  ? xr[l0 - 1] : 0.f;
                float xa = xr[l0];
                float xb = xr[l0 + 1];
                float xc = (p < 31) ? xr[l0 + 2] : 0.f;
                float y00 = fmaf(w02, xb, fmaf(w01, xa, fmaf(w00, xm, b0)));
                float y01 = fmaf(w02, xc, fmaf(w01, xb, fmaf(w00, xa, b0)));
                float y10 = fmaf(w12, xb, fmaf(w11, xa, fmaf(w10, xm, b1)));
                float y11 = fmaf(w12, xc, fmaf(w11, xb, fmaf(w10, xa, b1)));
                float v0 = fmaxf(fmaxf(y00, y01), 0.f);
                float v1 = fmaxf(fmaxf(y10, y11), 0.f);
                *(__half2*)(A1 + r * 1360 + (1 + p) * 40 + ic0) =
                    __floats2half2_rn(v0, v1);
            }
        }
    }
    __syncthreads();

    // ---- conv2: 3 shifted GEMMs, M=32 pos, N=64, K=96 ----------------------
    #pragma unroll 1
    for (int rr = 0; rr < 4; rr++) {
        const int r = wid * 4 + rr;
        float c[2][8][4] = {};
        const __half* Abase = A1 + r * 1360 + qrow * 40 + 2 * qc;

        #pragma unroll
        for (int ks = 0; ks < 6; ks++) {
            const int s  = ks >> 1;
            const int kh = (ks & 1) << 4;
            const __half* ap = Abase + s * 40 + kh;
            unsigned a[2][4];
            #pragma unroll
            for (int t = 0; t < 2; t++) {
                const __half* app = ap + t * 640;
                a[t][0] = ldh2(app);        a[t][1] = ldh2(app + 320);
                a[t][2] = ldh2(app + 8);    a[t][3] = ldh2(app + 328);
            }
            const __half* bp0 = Wt + qrow * 104 + s * 32 + kh + 2 * qc;
            #pragma unroll
            for (int n = 0; n < 8; n++) {
                const __half* bp = bp0 + n * 832;     // n*8*104
                unsigned b0 = ldh2(bp), b1 = ldh2(bp + 8);
                mma_f16(c[0][n], a[0][0], a[0][1], a[0][2], a[0][3], b0, b1);
                mma_f16(c[1][n], a[1][0], a[1][1], a[1][2], a[1][3], b0, b1);
            }
        }

        // bias + relu + maxpool2 (shfl) -> g_a2h pos-major
        __half2* dst = (__half2*)(g_a2h + (size_t)(row0 + r) * 1024);
        #pragma unroll
        for (int t = 0; t < 2; t++) {
            #pragma unroll
            for (int n = 0; n < 8; n++) {
                int j0 = n * 8 + 2 * qc;
                float b0 = C2B[j0], b1 = C2B[j0 + 1];
                float v0 = fmaxf(c[t][n][0] + b0, 0.f);
                float v1 = fmaxf(c[t][n][1] + b1, 0.f);
                float v2 = fmaxf(c[t][n][2] + b0, 0.f);
                float v3 = fmaxf(c[t][n][3] + b1, 0.f);
                v0 = fmaxf(v0, __shfl_xor_sync(0xffffffffu, v0, 4));
                v1 = fmaxf(v1, __shfl_xor_sync(0xffffffffu, v1, 4));
                v2 = fmaxf(v2, __shfl_xor_sync(0xffffffffu, v2, 4));
                v3 = fmaxf(v3, __shfl_xor_sync(0xffffffffu, v3, 4));
                if (!(lane & 4)) {
                    int q = t * 8 + (lane >> 3);
                    dst[(q * 64 + j0) >> 1]       = __floats2half2_rn(v0, v1);
                    dst[((q + 4) * 64 + j0) >> 1] = __floats2half2_rn(v2, v3);
                }
            }
        }
    }
}

// ===========================================================================
// K2: fc GEMM (128 rows, K=1024) + fused head. smem bytes:
//   Ah  half 2x[128][72] @ 0      (36864)
//   Wth half 2x[64][72]  @ 36864  (18432)
//   QC f32 [24] @ 55296, QS [24] @ 55392 -> 55488 B
//   Hf f32 [128][68] aliases Ah after GEMM (34816 B)
// ===========================================================================
#define K2_SMEM 55488

__global__ __launch_bounds__(256, 2)
void k2_fc_head(const float* __restrict__ fcb,
                const float* __restrict__ prew, const float* __restrict__ preb,
                const float* __restrict__ qp,
                const float* __restrict__ postw, const float* __restrict__ postb,
                float* __restrict__ out)
{
    extern __shared__ __align__(16) unsigned char smraw[];
    __half* Ah  = (__half*)smraw;
    __half* Wth = (__half*)(smraw + 36864);
    float*  QC  = (float*)(smraw + 55296);
    float*  QS  = (float*)(smraw + 55392);
    float*  Hf  = (float*)smraw;

    const int tid  = threadIdx.x;
    const int wid  = tid >> 5;
    const int lane = tid & 31;
    const int qrow = lane >> 2;
    const int qc   = lane & 3;
    const int m0   = blockIdx.x * 128;
    const int mg   = wid & 3;
    const int ng   = wid >> 2;

    if (tid < 24) {
        float s, cc;
        sincosf(qp[tid] * 0.5f, &s, &cc);
        QC[tid] = cc; QS[tid] = s;
    }

    auto stage = [&](int buf, int ch) {
        const __half* srcA = g_a2h + (size_t)m0 * 1024 + ch * 64;
        __half* dA = Ah + buf * 9216;
        #pragma unroll
        for (int i = 0; i < 4; i++) {
            int idx = tid + i * 256;          // 1024 x 16B
            int r = idx >> 3, kv = idx & 7;
            cpa16(dA + r * 72 + kv * 8, srcA + (size_t)r * 1024 + kv * 8);
        }
        const __half* srcW = g_fcwt + ch * 64;
        __half* dW = Wth + buf * 4608;
        #pragma unroll
        for (int i = 0; i < 2; i++) {
            int idx = tid + i * 256;          // 512 x 16B
            int r = idx >> 3, kv = idx & 7;
            cpa16(dW + r * 72 + kv * 8, srcW + (size_t)r * 1024 + kv * 8);
        }
        asm volatile("cp.async.commit_group;\n");
    };

    float c[2][4][4] = {};
    int buf = 0;
    stage(0, 0);

    #pragma unroll 1
    for (int ch = 0; ch < 16; ch++) {
        if (ch < 15) {
            stage(buf ^ 1, ch + 1);
            asm volatile("cp.async.wait_group 1;\n");
        } else {
            asm volatile("cp.async.wait_group 0;\n");
        }
        __syncthreads();

        const __half* Ab = Ah + buf * 9216 + (mg * 32 + qrow) * 72 + 2 * qc;
        const __half* Bb = Wth + buf * 4608 + (ng * 32 + qrow) * 72 + 2 * qc;
        #pragma unroll
        for (int ks = 0; ks < 4; ks++) {
            unsigned a[2][4];
            #pragma unroll
            for (int t = 0; t < 2; t++) {
                const __half* ap = Ab + t * 1152 + ks * 16;   // t*16*72
                a[t][0] = ldh2(ap);       a[t][1] = ldh2(ap + 576);
                a[t][2] = ldh2(ap + 8);   a[t][3] = ldh2(ap + 584);
            }
            #pragma unroll
            for (int n = 0; n < 4; n++) {
                const __half* bp = Bb + n * 576 + ks * 16;    // n*8*72
                unsigned b0 = ldh2(bp), b1 = ldh2(bp + 8);
                mma_f16(c[0][n], a[0][0], a[0][1], a[0][2], a[0][3], b0, b1);
                mma_f16(c[1][n], a[1][0], a[1][1], a[1][2], a[1][3], b0, b1);
            }
        }
        __syncthreads();
        buf ^= 1;
    }

    // ---- bias + relu -> Hf -------------------------------------------------
    #pragma unroll
    for (int t = 0; t < 2; t++) {
        #pragma unroll
        for (int n = 0; n < 4; n++) {
            int j0 = ng * 32 + n * 8 + 2 * qc;
            int m  = mg * 32 + t * 16 + qrow;
            float b0 = __ldg(fcb + j0), b1 = __ldg(fcb + j0 + 1);
            *(float2*)(Hf + m * 68 + j0) =
                make_float2(fmaxf(c[t][n][0] + b0, 0.f), fmaxf(c[t][n][1] + b1, 0.f));
            *(float2*)(Hf + (m + 8) * 68 + j0) =
                make_float2(fmaxf(c[t][n][2] + b0, 0.f), fmaxf(c[t][n][3] + b1, 0.f));
        }
    }
    __syncthreads();

    // ---- quantum head: one thread per row ----------------------------------
    if (tid < 128) {
        const float* hrow = Hf + tid * 68;
        float4 acc = *(const float4*)preb;
        #pragma unroll
        for (int j4 = 0; j4 < 16; j4++) {
            float4 h4 = *(const float4*)(hrow + j4 * 4);
            float4 wa = __ldg((const float4*)prew + (j4 * 4 + 0));
            float4 wb = __ldg((const float4*)prew + (j4 * 4 + 1));
            float4 wc = __ldg((const float4*)prew + (j4 * 4 + 2));
            float4 wd = __ldg((const float4*)prew + (j4 * 4 + 3));
            acc.x = fmaf(h4.x, wa.x, acc.x); acc.y = fmaf(h4.x, wa.y, acc.y);
            acc.z = fmaf(h4.x, wa.z, acc.z); acc.w = fmaf(h4.x, wa.w, acc.w);
            acc.x = fmaf(h4.y, wb.x, acc.x); acc.y = fmaf(h4.y, wb.y, acc.y);
            acc.z = fmaf(h4.y, wb.z, acc.z); acc.w = fmaf(h4.y, wb.w, acc.w);
            acc.x = fmaf(h4.z, wc.x, acc.x); acc.y = fmaf(h4.z, wc.y, acc.y);
            acc.z = fmaf(h4.z, wc.z, acc.z); acc.w = fmaf(h4.z, wc.w, acc.w);
            acc.x = fmaf(h4.w, wd.x, acc.x); acc.y = fmaf(h4.w, wd.y, acc.y);
            acc.z = fmaf(h4.w, wd.z, acc.z); acc.w = fmaf(h4.w, wd.w, acc.w);
        }
        const float PI_2 = 1.57079632679489662f;
        float th[4] = { tanhf(acc.x) * PI_2, tanhf(acc.y) * PI_2,
                        tanhf(acc.z) * PI_2, tanhf(acc.w) * PI_2 };

        float st[16];
        #pragma unroll
        for (int i = 0; i < 16; i++) st[i] = 0.25f;

        #pragma unroll
        for (int w = 0; w < 4; w++) {
            float s, cc;
            sincosf(th[w] * 0.5f, &s, &cc);
            const int m = 8 >> w;
            #pragma unroll
            for (int i = 0; i < 16; i++) {
                if (!(i & m)) {
                    int j = i | m;
                    float aa = st[i], bb = st[j];
                    st[i] = cc * aa - s * bb;
                    st[j] = s * aa + cc * bb;
                }
            }
        }
        #pragma unroll
        for (int k = 0; k < 6; k++) {
            #pragma unroll
            for (int i = 0; i < 16; i++)
                if ((i & 8) && !(i & 4)) { float tv = st[i]; st[i] = st[i|4]; st[i|4] = tv; }
            #pragma unroll
            for (int i = 0; i < 16; i++)
                if ((i & 2) && !(i & 1)) { float tv = st[i]; st[i] = st[i|1]; st[i|1] = tv; }
            #pragma unroll
            for (int i = 0; i < 16; i++)
                if ((i & 4) && !(i & 2)) { float tv = st[i]; st[i] = st[i|2]; st[i|2] = tv; }
            #pragma unroll
            for (int w = 0; w < 4; w++) {
                float cc = QC[k * 4 + w], s = QS[k * 4 + w];
                const int m = 8 >> w;
                #pragma unroll
                for (int i = 0; i < 16; i++) {
                    if (!(i & m)) {
                        int j = i | m;
                        float aa = st[i], bb = st[j];
                        st[i] = cc * aa - s * bb;
                        st[j] = s * aa + cc * bb;
                    }
                }
            }
        }
        float z0 = 0.f, z1 = 0.f, z2 = 0.f, z3 = 0.f;
        #pragma unroll
        for (int i = 0; i < 16; i++) {
            float p = st[i] * st[i];
            z0 += (i & 8) ? -p : p;
            z1 += (i & 4) ? -p : p;
            z2 += (i & 2) ? -p : p;
            z3 += (i & 1) ? -p : p;
        }
        float tacc = __ldg(postb);
        tacc = fmaf(z0, __ldg(postw + 0), tacc);
        tacc = fmaf(z1, __ldg(postw + 1), tacc);
        tacc = fmaf(z2, __ldg(postw + 2), tacc);
        tacc = fmaf(z3, __ldg(postw + 3), tacc);
        out[m0 + tid] = 1.f / (1.f + expf(-tacc));
    }
}

// ===========================================================================
extern "C" void kernel_launch(void* const* d_in, const int* in_sizes, int n_in,
                              void* d_out, int out_size)
{
    const float* x     = (const float*)d_in[0];
    const float* c1w   = (const float*)d_in[1];
    const float* c1b   = (const float*)d_in[2];
    const float* c2w   = (const float*)d_in[3];
    const float* c2b   = (const float*)d_in[4];
    const float* fcw   = (const float*)d_in[5];
    const float* fcb   = (const float*)d_in[6];
    const float* prew  = (const float*)d_in[7];
    const float* preb  = (const float*)d_in[8];
    const float* qp    = (const float*)d_in[9];
    const float* postw = (const float*)d_in[10];
    const float* postb = (const float*)d_in[11];

    const int B = in_sizes[0] / 64;

    cudaFuncSetAttribute(k1_conv, cudaFuncAttributeMaxDynamicSharedMemorySize, K1_SMEM);
    cudaFuncSetAttribute(k2_fc_head, cudaFuncAttributeMaxDynamicSharedMemorySize, K2_SMEM);

    k0_setup<<<280, 256>>>(c2w, fcw);
    k1_conv<<<B / 32, 256, K1_SMEM>>>(x, c1w, c1b, c2b);
    k2_fc_head<<<B / 128, 256, K2_SMEM>>>(fcb, prew, preb, qp, postw, postb,
                                          (float*)d_out);
}

// round 7
// speedup vs baseline: 7.9837x; 1.7174x over previous
#include <cuda_runtime.h>
#include <cuda_fp16.h>
#include <math.h>

// ---------------------------------------------------------------------------
// QuantumHybridCNN — fp16 tensor-core version, round 7 (round 6 + row fix).
// K1: (blocks<64 also transpose fc_w -> g_fcwt)
//     conv1 (HFMA2) + pool -> A1 half smem; conv2 = 3 shifted fp16 GEMMs with
//     hoisted B-frags (each row-group covers 8 rows); bias+relu+pool
//     -> coalesced STG.128 -> g_a2h
// K2: fc GEMM (cp.async double buffer) + fused quantum head
// ---------------------------------------------------------------------------

#define B_MAX 32768

__device__ __align__(16) __half g_a2h[B_MAX * 1024];   // 64 MB
__device__ __align__(16) __half g_fcwt[64 * 1024];     // 128 KB

// ---- helpers ---------------------------------------------------------------
__device__ __forceinline__ void mma_f16(float* c, unsigned a0, unsigned a1,
                                        unsigned a2, unsigned a3,
                                        unsigned b0, unsigned b1) {
    asm volatile(
        "mma.sync.aligned.m16n8k16.row.col.f32.f16.f16.f32 "
        "{%0,%1,%2,%3},{%4,%5,%6,%7},{%8,%9},{%0,%1,%2,%3};\n"
        : "+f"(c[0]), "+f"(c[1]), "+f"(c[2]), "+f"(c[3])
        : "r"(a0), "r"(a1), "r"(a2), "r"(a3), "r"(b0), "r"(b1));
}
__device__ __forceinline__ unsigned ldh2(const __half* p) {
    return *(const unsigned*)p;
}
__device__ __forceinline__ void cpa16(void* dst, const void* src) {
    unsigned d = (unsigned)__cvta_generic_to_shared(dst);
    asm volatile("cp.async.cg.shared.global [%0], [%1], 16;\n" :: "r"(d), "l"(src));
}

// ===========================================================================
// K1. smem layout (bytes):
//   A1   half [32 rows][34 pos][40]  @ 0       (87040)  pos 0/33 zero guards
//   Wt   half [64 oc][104]           @ 87040   (13312)
//   Xh/SCR                           @ 100352  (10240)  Xh: [32][68] half (conv1)
//                                                       SCR: 8 warps x 1280B (epi)
//   C1Wh half2 [16][3] @110592 (192), C1Bh half2[16] @110784 (64)
//   C2B  f32 [64] @110848 (256)  -> total 111104 B  (2 blocks/SM)
// ===========================================================================
#define K1_SMEM 111104

__global__ __launch_bounds__(256, 2)
void k1_conv(const float* __restrict__ x,
             const float* __restrict__ c1w, const float* __restrict__ c1b,
             const float* __restrict__ c2w, const float* __restrict__ c2b,
             const float* __restrict__ fcw)
{
    extern __shared__ __align__(16) unsigned char smraw[];
    __half*  A1   = (__half*)smraw;
    __half*  Wt   = (__half*)(smraw + 87040);
    __half*  Xh   = (__half*)(smraw + 100352);
    __half2* C1Wh = (__half2*)(smraw + 110592);
    __half2* C1Bh = (__half2*)(smraw + 110784);
    float*   C2B  = (float*)(smraw + 110848);

    const int tid  = threadIdx.x;
    const int wid  = tid >> 5;
    const int lane = tid & 31;
    const int qrow = lane >> 2;
    const int qc   = lane & 3;
    const int row0 = blockIdx.x * 32;

    // ---- fc_w transpose (blocks 0..63), independent of smem ---------------
    if (blockIdx.x < 64) {
        int f = blockIdx.x * 1024 + tid * 4;
        float4 v = *(const float4*)(fcw + f);
        int k = f >> 6, j = f & 63;
        int oc = k >> 4, p = k & 15;
        __half* d = g_fcwt + p * 64 + oc;
        d[(j + 0) * 1024] = __float2half_rn(v.x);
        d[(j + 1) * 1024] = __float2half_rn(v.y);
        d[(j + 2) * 1024] = __float2half_rn(v.z);
        d[(j + 3) * 1024] = __float2half_rn(v.w);
    }

    // ---- staging -----------------------------------------------------------
    {   // x -> Xh (half, row stride 68)
        const float4* xs = (const float4*)(x + row0 * 64);
        #pragma unroll
        for (int i = 0; i < 2; i++) {
            int idx = tid + i * 256;
            float4 f4 = xs[idx];
            int r = idx >> 4, c = (idx & 15) * 4;
            __half2* d = (__half2*)(Xh + r * 68 + c);
            d[0] = __floats2half2_rn(f4.x, f4.y);
            d[1] = __floats2half2_rn(f4.z, f4.w);
        }
    }
    if (tid < 48) {   // conv1 weights as half2 over ic pairs
        int icp = tid / 3, k = tid - icp * 3;
        C1Wh[icp * 3 + k] = __floats2half2_rn(c1w[(2 * icp) * 3 + k],
                                              c1w[(2 * icp + 1) * 3 + k]);
    }
    if (tid < 16) C1Bh[tid] = __floats2half2_rn(c1b[2 * tid], c1b[2 * tid + 1]);
    if (tid < 64) C2B[tid] = c2b[tid];
    // conv2_w (oc,ic,s) -> Wt[oc][s*32+ic]
    for (int g = tid; g < 6144; g += 256) {
        int oc = g / 96, rem = g - oc * 96;
        int ic = rem / 3, s = rem - ic * 3;
        Wt[oc * 104 + s * 32 + ic] = __float2half_rn(c2w[g]);
    }
    // zero guard rows (pos 0 and 33)
    #pragma unroll
    for (int i = 0; i < 4; i++) {
        int idx = tid + i * 256;
        int r = idx >> 5, rest = idx & 31;
        int pos = (rest & 16) ? 33 : 0;
        int icp = rest & 15;
        *(unsigned*)(A1 + r * 1360 + pos * 40 + icp * 2) = 0u;
    }
    __syncthreads();

    // ---- conv1 (HFMA2) + relu + maxpool2 -> A1 -----------------------------
    {
        const int icp = tid >> 4, pp = tid & 15;
        const __half2 w0 = C1Wh[icp * 3 + 0];
        const __half2 w1 = C1Wh[icp * 3 + 1];
        const __half2 w2 = C1Wh[icp * 3 + 2];
        const __half2 bb = C1Bh[icp];
        const __half2 zz = __float2half2_rn(0.f);
        const __half  zh = __float2half(0.f);
        for (int r = 0; r < 32; r++) {
            const __half* xr = Xh + r * 68;
            #pragma unroll
            for (int g = 0; g < 2; g++) {
                int p = pp + g * 16;
                int l0 = 2 * p;
                __half xm = (p > 0)  ? xr[l0 - 1] : zh;
                __half xa = xr[l0];
                __half xb = xr[l0 + 1];
                __half xc = (p < 31) ? xr[l0 + 2] : zh;
                __half2 xm2 = __half2half2(xm), xa2 = __half2half2(xa);
                __half2 xb2 = __half2half2(xb), xc2 = __half2half2(xc);
                __half2 y0 = __hfma2(w2, xb2, __hfma2(w1, xa2, __hfma2(w0, xm2, bb)));
                __half2 y1 = __hfma2(w2, xc2, __hfma2(w1, xb2, __hfma2(w0, xa2, bb)));
                __half2 v  = __hmax2(__hmax2(y0, y1), zz);
                *(__half2*)(A1 + r * 1360 + (1 + p) * 40 + 2 * icp) = v;
            }
        }
    }
    __syncthreads();

    // ---- conv2: 3 shifted GEMMs with hoisted B-frags -----------------------
    const int rg = wid >> 1;          // row group: rows 8rg..8rg+7
    const int nh = wid & 1;           // oc half: 32 oc

    unsigned bf[6][4][2];
    #pragma unroll
    for (int ks = 0; ks < 6; ks++) {
        const int s = ks >> 1, kh = (ks & 1) << 4;
        const __half* bp0 = Wt + (nh * 32 + qrow) * 104 + s * 32 + kh + 2 * qc;
        #pragma unroll
        for (int n = 0; n < 4; n++) {
            const __half* bp = bp0 + n * 832;       // n*8*104
            bf[ks][n][0] = ldh2(bp);
            bf[ks][n][1] = ldh2(bp + 8);
        }
    }

    __half* scr = (__half*)(smraw + 100352) + wid * 640;   // 16 x 40 halves

    #pragma unroll 1
    for (int rr = 0; rr < 8; rr++) {
        const int r = rg * 8 + rr;                  // FIX: 4 groups x 8 rows = 32
        float c[2][4][4] = {};
        const __half* Abase = A1 + r * 1360 + qrow * 40 + 2 * qc;

        #pragma unroll
        for (int ks = 0; ks < 6; ks++) {
            const int s = ks >> 1, kh = (ks & 1) << 4;
            const __half* ap = Abase + s * 40 + kh;
            unsigned a[2][4];
            #pragma unroll
            for (int t = 0; t < 2; t++) {
                const __half* app = ap + t * 640;
                a[t][0] = ldh2(app);        a[t][1] = ldh2(app + 320);
                a[t][2] = ldh2(app + 8);    a[t][3] = ldh2(app + 328);
            }
            #pragma unroll
            for (int n = 0; n < 4; n++) {
                mma_f16(c[0][n], a[0][0], a[0][1], a[0][2], a[0][3],
                        bf[ks][n][0], bf[ks][n][1]);
                mma_f16(c[1][n], a[1][0], a[1][1], a[1][2], a[1][3],
                        bf[ks][n][0], bf[ks][n][1]);
            }
        }

        // bias + relu + maxpool2 (shfl) -> per-warp scratch (stride 40)
        #pragma unroll
        for (int t = 0; t < 2; t++) {
            #pragma unroll
            for (int n = 0; n < 4; n++) {
                int jl = n * 8 + 2 * qc;
                float b0 = C2B[nh * 32 + jl], b1 = C2B[nh * 32 + jl + 1];
                float v0 = fmaxf(c[t][n][0] + b0, 0.f);
                float v1 = fmaxf(c[t][n][1] + b1, 0.f);
                float v2 = fmaxf(c[t][n][2] + b0, 0.f);
                float v3 = fmaxf(c[t][n][3] + b1, 0.f);
                v0 = fmaxf(v0, __shfl_xor_sync(0xffffffffu, v0, 4));
                v1 = fmaxf(v1, __shfl_xor_sync(0xffffffffu, v1, 4));
                v2 = fmaxf(v2, __shfl_xor_sync(0xffffffffu, v2, 4));
                v3 = fmaxf(v3, __shfl_xor_sync(0xffffffffu, v3, 4));
                if (!(lane & 4)) {
                    int q = t * 8 + (lane >> 3);
                    *(__half2*)(scr + q * 40 + jl)       = __floats2half2_rn(v0, v1);
                    *(__half2*)(scr + (q + 4) * 40 + jl) = __floats2half2_rn(v2, v3);
                }
            }
        }
        __syncwarp();

        // coalesced copy scratch -> g_a2h row r (STG.128)
        __half* dst = g_a2h + (size_t)(row0 + r) * 1024 + nh * 32;
        #pragma unroll
        for (int pass = 0; pass < 2; pass++) {
            int p  = (lane >> 2) + pass * 8;
            int ch = lane & 3;
            uint4 v = *(const uint4*)(scr + p * 40 + ch * 8);
            *(uint4*)(dst + p * 64 + ch * 8) = v;
        }
        __syncwarp();
    }
}

// ===========================================================================
// K2: fc GEMM (128 rows, K=1024) + fused head
// ===========================================================================
#define K2_SMEM 55488

__global__ __launch_bounds__(256, 2)
void k2_fc_head(const float* __restrict__ fcb,
                const float* __restrict__ prew, const float* __restrict__ preb,
                const float* __restrict__ qp,
                const float* __restrict__ postw, const float* __restrict__ postb,
                float* __restrict__ out)
{
    extern __shared__ __align__(16) unsigned char smraw[];
    __half* Ah  = (__half*)smraw;
    __half* Wth = (__half*)(smraw + 36864);
    float*  QC  = (float*)(smraw + 55296);
    float*  QS  = (float*)(smraw + 55392);
    float*  Hf  = (float*)smraw;

    const int tid  = threadIdx.x;
    const int wid  = tid >> 5;
    const int lane = tid & 31;
    const int qrow = lane >> 2;
    const int qc   = lane & 3;
    const int m0   = blockIdx.x * 128;
    const int mg   = wid & 3;
    const int ng   = wid >> 2;

    if (tid < 24) {
        float s, cc;
        sincosf(qp[tid] * 0.5f, &s, &cc);
        QC[tid] = cc; QS[tid] = s;
    }

    auto stage = [&](int buf, int ch) {
        const __half* srcA = g_a2h + (size_t)m0 * 1024 + ch * 64;
        __half* dA = Ah + buf * 9216;
        #pragma unroll
        for (int i = 0; i < 4; i++) {
            int idx = tid + i * 256;
            int r = idx >> 3, kv = idx & 7;
            cpa16(dA + r * 72 + kv * 8, srcA + (size_t)r * 1024 + kv * 8);
        }
        const __half* srcW = g_fcwt + ch * 64;
        __half* dW = Wth + buf * 4608;
        #pragma unroll
        for (int i = 0; i < 2; i++) {
            int idx = tid + i * 256;
            int r = idx >> 3, kv = idx & 7;
            cpa16(dW + r * 72 + kv * 8, srcW + (size_t)r * 1024 + kv * 8);
        }
        asm volatile("cp.async.commit_group;\n");
    };

    float c[2][4][4] = {};
    int buf = 0;
    stage(0, 0);

    #pragma unroll 1
    for (int ch = 0; ch < 16; ch++) {
        if (ch < 15) {
            stage(buf ^ 1, ch + 1);
            asm volatile("cp.async.wait_group 1;\n");
        } else {
            asm volatile("cp.async.wait_group 0;\n");
        }
        __syncthreads();

        const __half* Ab = Ah + buf * 9216 + (mg * 32 + qrow) * 72 + 2 * qc;
        const __half* Bb = Wth + buf * 4608 + (ng * 32 + qrow) * 72 + 2 * qc;
        #pragma unroll
        for (int ks = 0; ks < 4; ks++) {
            unsigned a[2][4];
            #pragma unroll
            for (int t = 0; t < 2; t++) {
                const __half* ap = Ab + t * 1152 + ks * 16;
                a[t][0] = ldh2(ap);       a[t][1] = ldh2(ap + 576);
                a[t][2] = ldh2(ap + 8);   a[t][3] = ldh2(ap + 584);
            }
            #pragma unroll
            for (int n = 0; n < 4; n++) {
                const __half* bp = Bb + n * 576 + ks * 16;
                unsigned b0 = ldh2(bp), b1 = ldh2(bp + 8);
                mma_f16(c[0][n], a[0][0], a[0][1], a[0][2], a[0][3], b0, b1);
                mma_f16(c[1][n], a[1][0], a[1][1], a[1][2], a[1][3], b0, b1);
            }
        }
        __syncthreads();
        buf ^= 1;
    }

    // ---- bias + relu -> Hf -------------------------------------------------
    #pragma unroll
    for (int t = 0; t < 2; t++) {
        #pragma unroll
        for (int n = 0; n < 4; n++) {
            int j0 = ng * 32 + n * 8 + 2 * qc;
            int m  = mg * 32 + t * 16 + qrow;
            float b0 = __ldg(fcb + j0), b1 = __ldg(fcb + j0 + 1);
            *(float2*)(Hf + m * 68 + j0) =
                make_float2(fmaxf(c[t][n][0] + b0, 0.f), fmaxf(c[t][n][1] + b1, 0.f));
            *(float2*)(Hf + (m + 8) * 68 + j0) =
                make_float2(fmaxf(c[t][n][2] + b0, 0.f), fmaxf(c[t][n][3] + b1, 0.f));
        }
    }
    __syncthreads();

    // ---- quantum head: one thread per row ----------------------------------
    if (tid < 128) {
        const float* hrow = Hf + tid * 68;
        float4 acc = *(const float4*)preb;
        #pragma unroll
        for (int j4 = 0; j4 < 16; j4++) {
            float4 h4 = *(const float4*)(hrow + j4 * 4);
            float4 wa = __ldg((const float4*)prew + (j4 * 4 + 0));
            float4 wb = __ldg((const float4*)prew + (j4 * 4 + 1));
            float4 wc = __ldg((const float4*)prew + (j4 * 4 + 2));
            float4 wd = __ldg((const float4*)prew + (j4 * 4 + 3));
            acc.x = fmaf(h4.x, wa.x, acc.x); acc.y = fmaf(h4.x, wa.y, acc.y);
            acc.z = fmaf(h4.x, wa.z, acc.z); acc.w = fmaf(h4.x, wa.w, acc.w);
            acc.x = fmaf(h4.y, wb.x, acc.x); acc.y = fmaf(h4.y, wb.y, acc.y);
            acc.z = fmaf(h4.y, wb.z, acc.z); acc.w = fmaf(h4.y, wb.w, acc.w);
            acc.x = fmaf(h4.z, wc.x, acc.x); acc.y = fmaf(h4.z, wc.y, acc.y);
            acc.z = fmaf(h4.z, wc.z, acc.z); acc.w = fmaf(h4.z, wc.w, acc.w);
            acc.x = fmaf(h4.w, wd.x, acc.x); acc.y = fmaf(h4.w, wd.y, acc.y);
            acc.z = fmaf(h4.w, wd.z, acc.z); acc.w = fmaf(h4.w, wd.w, acc.w);
        }
        const float PI_2 = 1.57079632679489662f;
        float th[4] = { tanhf(acc.x) * PI_2, tanhf(acc.y) * PI_2,
                        tanhf(acc.z) * PI_2, tanhf(acc.w) * PI_2 };

        float st[16];
        #pragma unroll
        for (int i = 0; i < 16; i++) st[i] = 0.25f;

        #pragma unroll
        for (int w = 0; w < 4; w++) {
            float s, cc;
            sincosf(th[w] * 0.5f, &s, &cc);
            const int m = 8 >> w;
            #pragma unroll
            for (int i = 0; i < 16; i++) {
                if (!(i & m)) {
                    int j = i | m;
                    float aa = st[i], bb = st[j];
                    st[i] = cc * aa - s * bb;
                    st[j] = s * aa + cc * bb;
                }
            }
        }
        #pragma unroll
        for (int k = 0; k < 6; k++) {
            #pragma unroll
            for (int i = 0; i < 16; i++)
                if ((i & 8) && !(i & 4)) { float tv = st[i]; st[i] = st[i|4]; st[i|4] = tv; }
            #pragma unroll
            for (int i = 0; i < 16; i++)
                if ((i & 2) && !(i & 1)) { float tv = st[i]; st[i] = st[i|1]; st[i|1] = tv; }
            #pragma unroll
            for (int i = 0; i < 16; i++)
                if ((i & 4) && !(i & 2)) { float tv = st[i]; st[i] = st[i|2]; st[i|2] = tv; }
            #pragma unroll
            for (int w = 0; w < 4; w++) {
                float cc = QC[k * 4 + w], s = QS[k * 4 + w];
                const int m = 8 >> w;
                #pragma unroll
                for (int i = 0; i < 16; i++) {
                    if (!(i & m)) {
                        int j = i | m;
                        float aa = st[i], bb = st[j];
                        st[i] = cc * aa - s * bb;
                        st[j] = s * aa + cc * bb;
                    }
                }
            }
        }
        float z0 = 0.f, z1 = 0.f, z2 = 0.f, z3 = 0.f;
        #pragma unroll
        for (int i = 0; i < 16; i++) {
            float p = st[i] * st[i];
            z0 += (i & 8) ? -p : p;
            z1 += (i & 4) ? -p : p;
            z2 += (i & 2) ? -p : p;
            z3 += (i & 1) ? -p : p;
        }
        float tacc = __ldg(postb);
        tacc = fmaf(z0, __ldg(postw + 0), tacc);
        tacc = fmaf(z1, __ldg(postw + 1), tacc);
        tacc = fmaf(z2, __ldg(postw + 2), tacc);
        tacc = fmaf(z3, __ldg(postw + 3), tacc);
        out[m0 + tid] = 1.f / (1.f + expf(-tacc));
    }
}

// ===========================================================================
extern "C" void kernel_launch(void* const* d_in, const int* in_sizes, int n_in,
                              void* d_out, int out_size)
{
    const float* x     = (const float*)d_in[0];
    const float* c1w   = (const float*)d_in[1];
    const float* c1b   = (const float*)d_in[2];
    const float* c2w   = (const float*)d_in[3];
    const float* c2b   = (const float*)d_in[4];
    const float* fcw   = (const float*)d_in[5];
    const float* fcb   = (const float*)d_in[6];
    const float* prew  = (const float*)d_in[7];
    const float* preb  = (const float*)d_in[8];
    const float* qp    = (const float*)d_in[9];
    const float* postw = (const float*)d_in[10];
    const float* postb = (const float*)d_in[11];

    const int B = in_sizes[0] / 64;

    cudaFuncSetAttribute(k1_conv, cudaFuncAttributeMaxDynamicSharedMemorySize, K1_SMEM);
    cudaFuncSetAttribute(k2_fc_head, cudaFuncAttributeMaxDynamicSharedMemorySize, K2_SMEM);

    k1_conv<<<B / 32, 256, K1_SMEM>>>(x, c1w, c1b, c2w, c2b, fcw);
    k2_fc_head<<<B / 128, 256, K2_SMEM>>>(fcb, prew, preb, qp, postw, postb,
                                          (float*)d_out);
}

// round 8
// speedup vs baseline: 8.7942x; 1.1015x over previous
#include <cuda_runtime.h>
#include <cuda_fp16.h>
#include <math.h>

// ---------------------------------------------------------------------------
// QuantumHybridCNN — fp16 tensor cores, round 8.
// K1: conv1(HFMA2)+pool -> A1 (stride 36, zero guards); conv2 = 3 shifted
//     fp16 GEMMs with PERMUTED M-rows so maxpool partners live in one thread
//     (no shfl epilogue); coalesced STG.128 -> g_a2h.  blocks<64: fc_w transp.
// K2: fc GEMM, 4-stage cp.async pipeline (3 chunks in flight), fused head.
// ---------------------------------------------------------------------------

#define B_MAX 32768

__device__ __align__(16) __half g_a2h[B_MAX * 1024];   // 64 MB
__device__ __align__(16) __half g_fcwt[64 * 1024];     // 128 KB

// ---- helpers ---------------------------------------------------------------
__device__ __forceinline__ void mma_f16(float* c, unsigned a0, unsigned a1,
                                        unsigned a2, unsigned a3,
                                        unsigned b0, unsigned b1) {
    asm volatile(
        "mma.sync.aligned.m16n8k16.row.col.f32.f16.f16.f32 "
        "{%0,%1,%2,%3},{%4,%5,%6,%7},{%8,%9},{%0,%1,%2,%3};\n"
        : "+f"(c[0]), "+f"(c[1]), "+f"(c[2]), "+f"(c[3])
        : "r"(a0), "r"(a1), "r"(a2), "r"(a3), "r"(b0), "r"(b1));
}
__device__ __forceinline__ unsigned ldh2(const __half* p) {
    return *(const unsigned*)p;
}
__device__ __forceinline__ void cpa16(void* dst, const void* src) {
    unsigned d = (unsigned)__cvta_generic_to_shared(dst);
    asm volatile("cp.async.cg.shared.global [%0], [%1], 16;\n" :: "r"(d), "l"(src));
}

// ===========================================================================
// K1. smem (bytes):
//   A1   half [32 r][34 pos][36]  @ 0       (78336)  pos 0/33 zero guards
//   Wt   half [64 oc][104]        @ 78336   (13312)
//   Xh/SCR                        @ 91648   (10240)  Xh [32][68] h / 8x1280B
//   C1Wh @101888 (192)  C1Bh @102080 (64)  C2B @102144 (256) -> 102400 B
// ===========================================================================
#define K1_SMEM 102400
#define A1_RSTR 1224     // 34*36 halves per batch row
#define A1_PSTR 36       // halves per position

__global__ __launch_bounds__(256, 2)
void k1_conv(const float* __restrict__ x,
             const float* __restrict__ c1w, const float* __restrict__ c1b,
             const float* __restrict__ c2w, const float* __restrict__ c2b,
             const float* __restrict__ fcw)
{
    extern __shared__ __align__(16) unsigned char smraw[];
    __half*  A1   = (__half*)smraw;
    __half*  Wt   = (__half*)(smraw + 78336);
    __half*  Xh   = (__half*)(smraw + 91648);
    __half2* C1Wh = (__half2*)(smraw + 101888);
    __half2* C1Bh = (__half2*)(smraw + 102080);
    float*   C2B  = (float*)(smraw + 102144);

    const int tid  = threadIdx.x;
    const int wid  = tid >> 5;
    const int lane = tid & 31;
    const int qrow = lane >> 2;
    const int qc   = lane & 3;
    const int row0 = blockIdx.x * 32;

    // ---- fc_w transpose (blocks 0..63) -------------------------------------
    if (blockIdx.x < 64) {
        int f = blockIdx.x * 1024 + tid * 4;
        float4 v = *(const float4*)(fcw + f);
        int k = f >> 6, j = f & 63;
        int oc = k >> 4, p = k & 15;
        __half* d = g_fcwt + p * 64 + oc;
        d[(j + 0) * 1024] = __float2half_rn(v.x);
        d[(j + 1) * 1024] = __float2half_rn(v.y);
        d[(j + 2) * 1024] = __float2half_rn(v.z);
        d[(j + 3) * 1024] = __float2half_rn(v.w);
    }

    // ---- staging -----------------------------------------------------------
    {   // x -> Xh (half, row stride 68)
        const float4* xs = (const float4*)(x + row0 * 64);
        #pragma unroll
        for (int i = 0; i < 2; i++) {
            int idx = tid + i * 256;
            float4 f4 = xs[idx];
            int r = idx >> 4, c = (idx & 15) * 4;
            __half2* d = (__half2*)(Xh + r * 68 + c);
            d[0] = __floats2half2_rn(f4.x, f4.y);
            d[1] = __floats2half2_rn(f4.z, f4.w);
        }
    }
    if (tid < 48) {
        int icp = tid / 3, k = tid - icp * 3;
        C1Wh[icp * 3 + k] = __floats2half2_rn(c1w[(2 * icp) * 3 + k],
                                              c1w[(2 * icp + 1) * 3 + k]);
    }
    if (tid < 16) C1Bh[tid] = __floats2half2_rn(c1b[2 * tid], c1b[2 * tid + 1]);
    if (tid < 64) C2B[tid] = c2b[tid];
    // conv2_w (oc,ic,s) -> Wt[oc][s*32+ic]
    for (int g = tid; g < 6144; g += 256) {
        int oc = g / 96, rem = g - oc * 96;
        int ic = rem / 3, s = rem - ic * 3;
        Wt[oc * 104 + s * 32 + ic] = __float2half_rn(c2w[g]);
    }
    // zero guard rows (pos 0 and 33)
    #pragma unroll
    for (int i = 0; i < 4; i++) {
        int idx = tid + i * 256;
        int r = idx >> 5, rest = idx & 31;
        int pos = (rest & 16) ? 33 : 0;
        int icp = rest & 15;
        *(unsigned*)(A1 + r * A1_RSTR + pos * A1_PSTR + icp * 2) = 0u;
    }
    __syncthreads();

    // ---- conv1 (HFMA2) + relu + maxpool2 -> A1 -----------------------------
    {
        const int icp = tid >> 4, pp = tid & 15;
        const __half2 w0 = C1Wh[icp * 3 + 0];
        const __half2 w1 = C1Wh[icp * 3 + 1];
        const __half2 w2 = C1Wh[icp * 3 + 2];
        const __half2 bb = C1Bh[icp];
        const __half2 zz = __float2half2_rn(0.f);
        const __half  zh = __float2half(0.f);
        for (int r = 0; r < 32; r++) {
            const __half* xr = Xh + r * 68;
            #pragma unroll
            for (int g = 0; g < 2; g++) {
                int p = pp + g * 16;
                int l0 = 2 * p;
                __half xm = (p > 0)  ? xr[l0 - 1] : zh;
                __half xa = xr[l0];
                __half xb = xr[l0 + 1];
                __half xc = (p < 31) ? xr[l0 + 2] : zh;
                __half2 xm2 = __half2half2(xm), xa2 = __half2half2(xa);
                __half2 xb2 = __half2half2(xb), xc2 = __half2half2(xc);
                __half2 y0 = __hfma2(w2, xb2, __hfma2(w1, xa2, __hfma2(w0, xm2, bb)));
                __half2 y1 = __hfma2(w2, xc2, __hfma2(w1, xb2, __hfma2(w0, xa2, bb)));
                __half2 v  = __hmax2(__hmax2(y0, y1), zz);
                *(__half2*)(A1 + r * A1_RSTR + (1 + p) * A1_PSTR + 2 * icp) = v;
            }
        }
    }
    __syncthreads();

    // ---- conv2: 3 shifted GEMMs, permuted M (pool partners in-thread) ------
    // tile t, thread qrow: c[0]/c[1] = pos t*16+2*qrow ; c[2]/c[3] = +1
    const int rg = wid >> 1;          // rows 8rg..8rg+7
    const int nh = wid & 1;           // oc half

    unsigned bf[6][4][2];
    #pragma unroll
    for (int ks = 0; ks < 6; ks++) {
        const int s = ks >> 1, kh = (ks & 1) << 4;
        const __half* bp0 = Wt + (nh * 32 + qrow) * 104 + s * 32 + kh + 2 * qc;
        #pragma unroll
        for (int n = 0; n < 4; n++) {
            const __half* bp = bp0 + n * 832;
            bf[ks][n][0] = ldh2(bp);
            bf[ks][n][1] = ldh2(bp + 8);
        }
    }

    __half* scr = (__half*)(smraw + 91648) + wid * 640;   // 16 x 40 halves

    #pragma unroll 1
    for (int rr = 0; rr < 8; rr++) {
        const int r = rg * 8 + rr;
        float c[2][4][4] = {};
        const __half* Abase = A1 + r * A1_RSTR + 2 * qc;

        #pragma unroll
        for (int ks = 0; ks < 6; ks++) {
            const int s = ks >> 1, kh = (ks & 1) << 4;
            unsigned a[2][4];
            #pragma unroll
            for (int t = 0; t < 2; t++) {
                const __half* app = Abase + (t * 16 + 2 * qrow + s) * A1_PSTR + kh;
                a[t][0] = ldh2(app);        a[t][1] = ldh2(app + A1_PSTR);
                a[t][2] = ldh2(app + 8);    a[t][3] = ldh2(app + A1_PSTR + 8);
            }
            #pragma unroll
            for (int n = 0; n < 4; n++) {
                mma_f16(c[0][n], a[0][0], a[0][1], a[0][2], a[0][3],
                        bf[ks][n][0], bf[ks][n][1]);
                mma_f16(c[1][n], a[1][0], a[1][1], a[1][2], a[1][3],
                        bf[ks][n][0], bf[ks][n][1]);
            }
        }

        // pool (in-thread) + bias + relu -> scr
        #pragma unroll
        for (int t = 0; t < 2; t++) {
            #pragma unroll
            for (int n = 0; n < 4; n++) {
                int jl = n * 8 + 2 * qc;
                float b0 = C2B[nh * 32 + jl], b1 = C2B[nh * 32 + jl + 1];
                float p0 = fmaxf(fmaxf(c[t][n][0], c[t][n][2]) + b0, 0.f);
                float p1 = fmaxf(fmaxf(c[t][n][1], c[t][n][3]) + b1, 0.f);
                *(__half2*)(scr + (t * 8 + qrow) * 40 + jl) =
                    __floats2half2_rn(p0, p1);
            }
        }
        __syncwarp();

        // coalesced copy scratch -> g_a2h row r (STG.128)
        __half* dst = g_a2h + (size_t)(row0 + r) * 1024 + nh * 32;
        #pragma unroll
        for (int pass = 0; pass < 2; pass++) {
            int p  = (lane >> 2) + pass * 8;
            int ch = lane & 3;
            uint4 v = *(const uint4*)(scr + p * 40 + ch * 8);
            *(uint4*)(dst + p * 64 + ch * 8) = v;
        }
        __syncwarp();
    }
}

// ===========================================================================
// K2: fc GEMM, 4-stage cp.async pipeline. smem (bytes):
//   4 stages x { A [128][72] (18432) + W [64][72] (9216) } = 110592
//   QC @110592 (96), QS @110688 (96) -> 110784 B
//   Hf f32 [128][68] overlays stage 0/1 after GEMM.
// ===========================================================================
#define K2_SMEM 110784
#define STG_B   27648    // bytes per stage

__global__ __launch_bounds__(256, 2)
void k2_fc_head(const float* __restrict__ fcb,
                const float* __restrict__ prew, const float* __restrict__ preb,
                const float* __restrict__ qp,
                const float* __restrict__ postw, const float* __restrict__ postb,
                float* __restrict__ out)
{
    extern __shared__ __align__(16) unsigned char smraw[];
    float* QC = (float*)(smraw + 110592);
    float* QS = (float*)(smraw + 110688);
    float* Hf = (float*)smraw;

    const int tid  = threadIdx.x;
    const int wid  = tid >> 5;
    const int lane = tid & 31;
    const int qrow = lane >> 2;
    const int qc   = lane & 3;
    const int m0   = blockIdx.x * 128;
    const int mg   = wid & 3;
    const int ng   = wid >> 2;

    if (tid < 24) {
        float s, cc;
        sincosf(qp[tid] * 0.5f, &s, &cc);
        QC[tid] = cc; QS[tid] = s;
    }

    auto stage = [&](int st, int ch) {
        __half* dA = (__half*)(smraw + st * STG_B);
        __half* dW = (__half*)(smraw + st * STG_B + 18432);
        const __half* srcA = g_a2h + (size_t)m0 * 1024 + ch * 64;
        #pragma unroll
        for (int i = 0; i < 4; i++) {
            int idx = tid + i * 256;
            int r = idx >> 3, kv = idx & 7;
            cpa16(dA + r * 72 + kv * 8, srcA + (size_t)r * 1024 + kv * 8);
        }
        const __half* srcW = g_fcwt + ch * 64;
        #pragma unroll
        for (int i = 0; i < 2; i++) {
            int idx = tid + i * 256;
            int r = idx >> 3, kv = idx & 7;
            cpa16(dW + r * 72 + kv * 8, srcW + (size_t)r * 1024 + kv * 8);
        }
        asm volatile("cp.async.commit_group;\n");
    };

    float c[2][4][4] = {};
    stage(0, 0); stage(1, 1); stage(2, 2);

    #pragma unroll 1
    for (int ch = 0; ch < 16; ch++) {
        asm volatile("cp.async.wait_group 2;\n");   // chunk ch complete
        __syncthreads();                            // + all warps done mma(ch-1)
        if (ch < 13) stage((ch + 3) & 3, ch + 3);
        else         asm volatile("cp.async.commit_group;\n");  // empty group

        const __half* bufA = (__half*)(smraw + (ch & 3) * STG_B);
        const __half* bufW = bufA + 9216;           // halves: 18432 B offset
        const __half* Ab = bufA + (mg * 32 + qrow) * 72 + 2 * qc;
        const __half* Bb = bufW + (ng * 32 + qrow) * 72 + 2 * qc;
        #pragma unroll
        for (int ks = 0; ks < 4; ks++) {
            unsigned a[2][4];
            #pragma unroll
            for (int t = 0; t < 2; t++) {
                const __half* ap = Ab + t * 1152 + ks * 16;
                a[t][0] = ldh2(ap);       a[t][1] = ldh2(ap + 576);
                a[t][2] = ldh2(ap + 8);   a[t][3] = ldh2(ap + 584);
            }
            #pragma unroll
            for (int n = 0; n < 4; n++) {
                const __half* bp = Bb + n * 576 + ks * 16;
                unsigned b0 = ldh2(bp), b1 = ldh2(bp + 8);
                mma_f16(c[0][n], a[0][0], a[0][1], a[0][2], a[0][3], b0, b1);
                mma_f16(c[1][n], a[1][0], a[1][1], a[1][2], a[1][3], b0, b1);
            }
        }
    }
    __syncthreads();

    // ---- bias + relu -> Hf -------------------------------------------------
    #pragma unroll
    for (int t = 0; t < 2; t++) {
        #pragma unroll
        for (int n = 0; n < 4; n++) {
            int j0 = ng * 32 + n * 8 + 2 * qc;
            int m  = mg * 32 + t * 16 + qrow;
            float b0 = __ldg(fcb + j0), b1 = __ldg(fcb + j0 + 1);
            *(float2*)(Hf + m * 68 + j0) =
                make_float2(fmaxf(c[t][n][0] + b0, 0.f), fmaxf(c[t][n][1] + b1, 0.f));
            *(float2*)(Hf + (m + 8) * 68 + j0) =
                make_float2(fmaxf(c[t][n][2] + b0, 0.f), fmaxf(c[t][n][3] + b1, 0.f));
        }
    }
    __syncthreads();

    // ---- quantum head: one thread per row ----------------------------------
    if (tid < 128) {
        const float* hrow = Hf + tid * 68;
        float4 acc = *(const float4*)preb;
        #pragma unroll
        for (int j4 = 0; j4 < 16; j4++) {
            float4 h4 = *(const float4*)(hrow + j4 * 4);
            float4 wa = __ldg((const float4*)prew + (j4 * 4 + 0));
            float4 wb = __ldg((const float4*)prew + (j4 * 4 + 1));
            float4 wc = __ldg((const float4*)prew + (j4 * 4 + 2));
            float4 wd = __ldg((const float4*)prew + (j4 * 4 + 3));
            acc.x = fmaf(h4.x, wa.x, acc.x); acc.y = fmaf(h4.x, wa.y, acc.y);
            acc.z = fmaf(h4.x, wa.z, acc.z); acc.w = fmaf(h4.x, wa.w, acc.w);
            acc.x = fmaf(h4.y, wb.x, acc.x); acc.y = fmaf(h4.y, wb.y, acc.y);
            acc.z = fmaf(h4.y, wb.z, acc.z); acc.w = fmaf(h4.y, wb.w, acc.w);
            acc.x = fmaf(h4.z, wc.x, acc.x); acc.y = fmaf(h4.z, wc.y, acc.y);
            acc.z = fmaf(h4.z, wc.z, acc.z); acc.w = fmaf(h4.z, wc.w, acc.w);
            acc.x = fmaf(h4.w, wd.x, acc.x); acc.y = fmaf(h4.w, wd.y, acc.y);
            acc.z = fmaf(h4.w, wd.z, acc.z); acc.w = fmaf(h4.w, wd.w, acc.w);
        }
        const float PI_2 = 1.57079632679489662f;
        float th[4] = { tanhf(acc.x) * PI_2, tanhf(acc.y) * PI_2,
                        tanhf(acc.z) * PI_2, tanhf(acc.w) * PI_2 };

        float st[16];
        #pragma unroll
        for (int i = 0; i < 16; i++) st[i] = 0.25f;

        #pragma unroll
        for (int w = 0; w < 4; w++) {
            float s, cc;
            sincosf(th[w] * 0.5f, &s, &cc);
            const int m = 8 >> w;
            #pragma unroll
            for (int i = 0; i < 16; i++) {
                if (!(i & m)) {
                    int j = i | m;
                    float aa = st[i], bb = st[j];
                    st[i] = cc * aa - s * bb;
                    st[j] = s * aa + cc * bb;
                }
            }
        }
        #pragma unroll
        for (int k = 0; k < 6; k++) {
            #pragma unroll
            for (int i = 0; i < 16; i++)
                if ((i & 8) && !(i & 4)) { float tv = st[i]; st[i] = st[i|4]; st[i|4] = tv; }
            #pragma unroll
            for (int i = 0; i < 16; i++)
                if ((i & 2) && !(i & 1)) { float tv = st[i]; st[i] = st[i|1]; st[i|1] = tv; }
            #pragma unroll
            for (int i = 0; i < 16; i++)
                if ((i & 4) && !(i & 2)) { float tv = st[i]; st[i] = st[i|2]; st[i|2] = tv; }
            #pragma unroll
            for (int w = 0; w < 4; w++) {
                float cc = QC[k * 4 + w], s = QS[k * 4 + w];
                const int m = 8 >> w;
                #pragma unroll
                for (int i = 0; i < 16; i++) {
                    if (!(i & m)) {
                        int j = i | m;
                        float aa = st[i], bb = st[j];
                        st[i] = cc * aa - s * bb;
                        st[j] = s * aa + cc * bb;
                    }
                }
            }
        }
        float z0 = 0.f, z1 = 0.f, z2 = 0.f, z3 = 0.f;
        #pragma unroll
        for (int i = 0; i < 16; i++) {
            float p = st[i] * st[i];
            z0 += (i & 8) ? -p : p;
            z1 += (i & 4) ? -p : p;
            z2 += (i & 2) ? -p : p;
            z3 += (i & 1) ? -p : p;
        }
        float tacc = __ldg(postb);
        tacc = fmaf(z0, __ldg(postw + 0), tacc);
        tacc = fmaf(z1, __ldg(postw + 1), tacc);
        tacc = fmaf(z2, __ldg(postw + 2), tacc);
        tacc = fmaf(z3, __ldg(postw + 3), tacc);
        out[m0 + tid] = 1.f / (1.f + expf(-tacc));
    }
}

// ===========================================================================
extern "C" void kernel_launch(void* const* d_in, const int* in_sizes, int n_in,
                              void* d_out, int out_size)
{
    const float* x     = (const float*)d_in[0];
    const float* c1w   = (const float*)d_in[1];
    const float* c1b   = (const float*)d_in[2];
    const float* c2w   = (const float*)d_in[3];
    const float* c2b   = (const float*)d_in[4];
    const float* fcw   = (const float*)d_in[5];
    const float* fcb   = (const float*)d_in[6];
    const float* prew  = (const float*)d_in[7];
    const float* preb  = (const float*)d_in[8];
    const float* qp    = (const float*)d_in[9];
    const float* postw = (const float*)d_in[10];
    const float* postb = (const float*)d_in[11];

    const int B = in_sizes[0] / 64;

    cudaFuncSetAttribute(k1_conv, cudaFuncAttributeMaxDynamicSharedMemorySize, K1_SMEM);
    cudaFuncSetAttribute(k2_fc_head, cudaFuncAttributeMaxDynamicSharedMemorySize, K2_SMEM);

    k1_conv<<<B / 32, 256, K1_SMEM>>>(x, c1w, c1b, c2w, c2b, fcw);
    k2_fc_head<<<B / 128, 256, K2_SMEM>>>(fcb, prew, preb, qp, postw, postb,
                                          (float*)d_out);
}